// round 8
// baseline (speedup 1.0000x reference)
#include <cuda_runtime.h>
#include <cstdint>

// ---------------------------------------------------------------------------
// SAGEConv (mean agg):  out = relu(feat @ W_self + (scatter_mean(feat[src]->dst)) @ W_neigh + bias)
// N=100000, E=1600000, D_IN=D_OUT=64
//
// 3 kernels (stream-ordered, graph-capturable, no allocs):
//  1) zero_detect : zero scratch accumulators + detect int32-vs-int64 indices
//  2) edge        : half-warp per edge, LDG.128 gather + red.global.add.v4.f32 scatter
//  3) out_gemm    : tiled GEMM X[100K x 128] @ Wc[128 x 64] with packed f32x2 FMA
// ---------------------------------------------------------------------------

#define D_IN 64
#define D_OUT 64
#define MAX_NODES 100000

__device__ __align__(16) float g_neigh[MAX_NODES * D_IN];
__device__ float g_deg[MAX_NODES];
__device__ int g_idx64;

// ---------------------------------------------------------------------------
__global__ void zero_detect_kernel(const void* __restrict__ srcv,
                                   const void* __restrict__ dstv,
                                   int E, int N) {
    int tid = blockIdx.x * blockDim.x + threadIdx.x;
    int nthreads = gridDim.x * blockDim.x;
    int total4 = (N * D_IN) >> 2;
    float4 z = make_float4(0.f, 0.f, 0.f, 0.f);
    float4* p = reinterpret_cast<float4*>(g_neigh);
    for (int i = tid; i < total4; i += nthreads) p[i] = z;
    for (int i = tid; i < N; i += nthreads) g_deg[i] = 0.f;

    // Index-width detection: int32 data misread as int64 combines two random
    // indices -> value >= 2^32 with overwhelming probability over 2048 samples.
    if (blockIdx.x == 0) {
        __shared__ int bad;
        if (threadIdx.x == 0) bad = 0;
        __syncthreads();
        const long long* s64 = (const long long*)srcv;
        const long long* d64 = (const long long*)dstv;
        int samples = E < 2048 ? E : 2048;
        int lbad = 0;
        for (int i = threadIdx.x; i < samples; i += blockDim.x) {
            long long a = s64[i], b = d64[i];
            if (a < 0 || a >= (long long)N || b < 0 || b >= (long long)N) lbad = 1;
        }
        if (lbad) bad = 1;
        __syncthreads();
        if (threadIdx.x == 0) g_idx64 = bad ? 0 : 1;
    }
}

// ---------------------------------------------------------------------------
// Half-warp (16 lanes) per edge: each lane handles 4 floats (float4) of the
// 64-float row. Gather LDG.128, scatter via red.global.add.v4.f32 (no return).
__global__ void edge_kernel(const float* __restrict__ feat,
                            const void* __restrict__ srcv,
                            const void* __restrict__ dstv,
                            int E) {
    const bool i64 = (g_idx64 != 0);
    int hw = (blockIdx.x * blockDim.x + threadIdx.x) >> 4;
    int lane = threadIdx.x & 15;
    int nhw = (gridDim.x * blockDim.x) >> 4;

    const long long* s64 = (const long long*)srcv;
    const long long* d64 = (const long long*)dstv;
    const int* s32 = (const int*)srcv;
    const int* d32 = (const int*)dstv;

    for (int e = hw; e < E; e += nhw) {
        long long s, d;
        if (i64) {
            s = __ldg(s64 + e);
            d = __ldg(d64 + e);
        } else {
            s = (long long)__ldg(s32 + e);
            d = (long long)__ldg(d32 + e);
        }
        float4 v = __ldg(reinterpret_cast<const float4*>(feat + s * D_IN) + lane);
        float* dp = g_neigh + d * D_IN + lane * 4;
        asm volatile("red.global.add.v4.f32 [%0], {%1, %2, %3, %4};"
                     :: "l"(dp), "f"(v.x), "f"(v.y), "f"(v.z), "f"(v.w)
                     : "memory");
        if (lane == 0) atomicAdd(g_deg + d, 1.0f);
    }
}

// ---------------------------------------------------------------------------
// Packed f32x2 helpers (Blackwell double-rate fp32 path)
__device__ __forceinline__ unsigned long long pack2(float a, float b) {
    unsigned long long r;
    asm("mov.b64 %0, {%1, %2};" : "=l"(r) : "f"(a), "f"(b));
    return r;
}
__device__ __forceinline__ void unpack2(unsigned long long v, float& a, float& b) {
    asm("mov.b64 {%0, %1}, %2;" : "=f"(a), "=f"(b) : "l"(v));
}
#define FMA2(d, a, b) asm("fma.rn.f32x2 %0, %1, %2, %0;" : "+l"(d) : "l"(a), "l"(b))

// ---------------------------------------------------------------------------
// out = relu(X @ Wc + bias), X[n] = [feat[n] | neigh_sum[n]/max(deg,1)] (len 128)
// Wc = [W_self ; W_neigh]  (128 x 64)
// Block: 256 threads, tile = 128 nodes x 64 cols. Per-thread 8 nodes x 4 cols.
__global__ __launch_bounds__(256) void out_gemm_kernel(
    const float* __restrict__ feat,
    const float* __restrict__ Ws,
    const float* __restrict__ Wn,
    const float* __restrict__ bias,
    float* __restrict__ out,
    int N) {
    __shared__ float Wc[128][68];   // padded stride keeps float4 16B-aligned
    __shared__ float Xs[16][132];
    __shared__ float invd[128];
    __shared__ float bsh[64];

    int tid = threadIdx.x;
    int nb = blockIdx.x * 128;

    // load combined weight matrix
    for (int i = tid; i < 64 * 64; i += 256) {
        int k = i >> 6, c = i & 63;
        Wc[k][c] = Ws[i];
        Wc[64 + k][c] = Wn[i];
    }
    if (tid < 64) bsh[tid] = bias[tid];
    if (tid < 128) {
        int gn = nb + tid;
        float dg = (gn < N) ? g_deg[gn] : 1.f;
        invd[tid] = 1.f / fmaxf(dg, 1.f);
    }
    __syncthreads();

    const int r0 = (tid >> 4) * 8;   // 8 nodes
    const int c0 = (tid & 15) * 4;   // 4 cols

    unsigned long long acc[8][2];
#pragma unroll
    for (int i = 0; i < 8; i++) { acc[i][0] = 0ull; acc[i][1] = 0ull; }

    // loading role: 2 threads per node, each loads 8 contiguous k-values
    const int nl = tid >> 1;
    const int half = tid & 1;
    int gnl = nb + nl;
    if (gnl >= N) gnl = N - 1;  // clamped safe read; result masked at store
    const float iv = invd[nl];

#pragma unroll 1
    for (int kc = 0; kc < 8; kc++) {
        int kb = kc * 16 + half * 8;   // global k base for this thread's 8 values
        float4 a, b;
        if (kb < 64) {
            a = *reinterpret_cast<const float4*>(feat + (long long)gnl * 64 + kb);
            b = *reinterpret_cast<const float4*>(feat + (long long)gnl * 64 + kb + 4);
        } else {
            a = *reinterpret_cast<const float4*>(g_neigh + (long long)gnl * 64 + kb - 64);
            b = *reinterpret_cast<const float4*>(g_neigh + (long long)gnl * 64 + kb - 60);
            a.x *= iv; a.y *= iv; a.z *= iv; a.w *= iv;
            b.x *= iv; b.y *= iv; b.z *= iv; b.w *= iv;
        }
        __syncthreads();  // previous chunk fully consumed before overwrite
        int kk0 = half * 8;
        Xs[kk0 + 0][nl] = a.x; Xs[kk0 + 1][nl] = a.y;
        Xs[kk0 + 2][nl] = a.z; Xs[kk0 + 3][nl] = a.w;
        Xs[kk0 + 4][nl] = b.x; Xs[kk0 + 5][nl] = b.y;
        Xs[kk0 + 6][nl] = b.z; Xs[kk0 + 7][nl] = b.w;
        __syncthreads();

#pragma unroll
        for (int kk = 0; kk < 16; kk++) {
            int k = kc * 16 + kk;
            float4 w = *reinterpret_cast<const float4*>(&Wc[k][c0]);
            unsigned long long w01 = pack2(w.x, w.y);
            unsigned long long w23 = pack2(w.z, w.w);
            float4 xa = *reinterpret_cast<const float4*>(&Xs[kk][r0]);
            float4 xb = *reinterpret_cast<const float4*>(&Xs[kk][r0 + 4]);
            float xr[8] = {xa.x, xa.y, xa.z, xa.w, xb.x, xb.y, xb.z, xb.w};
#pragma unroll
            for (int i = 0; i < 8; i++) {
                unsigned long long xx = pack2(xr[i], xr[i]);
                FMA2(acc[i][0], xx, w01);
                FMA2(acc[i][1], xx, w23);
            }
        }
    }

    // epilogue: bias + relu + store
    float b0 = bsh[c0], b1 = bsh[c0 + 1], b2 = bsh[c0 + 2], b3 = bsh[c0 + 3];
#pragma unroll
    for (int i = 0; i < 8; i++) {
        int gn = nb + r0 + i;
        if (gn < N) {
            float o0, o1, o2, o3;
            unpack2(acc[i][0], o0, o1);
            unpack2(acc[i][1], o2, o3);
            float4 o;
            o.x = fmaxf(o0 + b0, 0.f);
            o.y = fmaxf(o1 + b1, 0.f);
            o.z = fmaxf(o2 + b2, 0.f);
            o.w = fmaxf(o3 + b3, 0.f);
            *reinterpret_cast<float4*>(out + (long long)gn * 64 + c0) = o;
        }
    }
}

// ---------------------------------------------------------------------------
extern "C" void kernel_launch(void* const* d_in, const int* in_sizes, int n_in,
                              void* d_out, int out_size) {
    const float* feat = (const float*)d_in[0];
    const void* src   = d_in[1];
    const void* dst   = d_in[2];
    const float* Ws   = (const float*)d_in[3];
    const float* Wn   = (const float*)d_in[4];
    const float* bias = (const float*)d_in[5];
    float* out = (float*)d_out;

    int N = in_sizes[0] / D_IN;
    int E = in_sizes[1];

    zero_detect_kernel<<<512, 256>>>(src, dst, E, N);
    edge_kernel<<<2048, 256>>>(feat, src, dst, E);
    int gblocks = (N + 127) / 128;
    out_gemm_kernel<<<gblocks, 256>>>(feat, Ws, Wn, bias, out, N);
}

// round 14
// speedup vs baseline: 1.0335x; 1.0335x over previous
#include <cuda_runtime.h>
#include <cstdint>

// ---------------------------------------------------------------------------
// SAGEConv (mean agg):  out = relu(feat @ W_self + (scatter_mean(feat[src]->dst)) @ W_neigh + bias)
// N=100000, E=1600000, D_IN=D_OUT=64
//
// Self-cleaning 2-kernel pipeline (graph-capturable, no allocs):
//  1) edge     : in-block index-width detect; half-warp per edge,
//                LDG.128 gather + red.global.add.v4.f32 scatter into g_neigh
//  2) out_gemm : tiled GEMM X[100K x 128] @ Wc[128 x 64] with packed f32x2 FMA;
//                epilogue ZEROES g_neigh/g_deg for the next replay
//                (first execution relies on static zero-init of device globals)
// ---------------------------------------------------------------------------

#define D_IN 64
#define D_OUT 64
#define MAX_NODES 100000

__device__ __align__(16) float g_neigh[MAX_NODES * D_IN];  // zero-init at load
__device__ float g_deg[MAX_NODES];                          // zero-init at load

// ---------------------------------------------------------------------------
// Edge scatter. Index width detected per-block from the first 32 entries:
// int32 data misread as int64 pairs two random indices -> hi word nonzero
// with probability ~1 per sample; 64 samples make misdetection impossible.
template <bool I64>
__device__ __forceinline__ void edge_loop(const float* __restrict__ feat,
                                          const void* __restrict__ srcv,
                                          const void* __restrict__ dstv,
                                          int E, int hw, int lane, int nhw) {
    const long long* s64 = (const long long*)srcv;
    const long long* d64 = (const long long*)dstv;
    const int* s32 = (const int*)srcv;
    const int* d32 = (const int*)dstv;
#pragma unroll 2
    for (int e = hw; e < E; e += nhw) {
        long long s, d;
        if (I64) {
            s = __ldg(s64 + e);
            d = __ldg(d64 + e);
        } else {
            s = (long long)__ldg(s32 + e);
            d = (long long)__ldg(d32 + e);
        }
        float4 v = __ldg(reinterpret_cast<const float4*>(feat + s * D_IN) + lane);
        float* dp = g_neigh + d * D_IN + lane * 4;
        asm volatile("red.global.add.v4.f32 [%0], {%1, %2, %3, %4};"
                     :: "l"(dp), "f"(v.x), "f"(v.y), "f"(v.z), "f"(v.w)
                     : "memory");
        if (lane == 0) atomicAdd(g_deg + d, 1.0f);
    }
}

__global__ void edge_kernel(const float* __restrict__ feat,
                            const void* __restrict__ srcv,
                            const void* __restrict__ dstv,
                            int E, int N) {
    __shared__ int s_i64;
    if (threadIdx.x < 32) {
        int i = threadIdx.x < E ? threadIdx.x : 0;
        long long a = __ldg((const long long*)srcv + i);
        long long b = __ldg((const long long*)dstv + i);
        int lbad = (a < 0 || a >= (long long)N || b < 0 || b >= (long long)N) ? 1 : 0;
        unsigned m = __ballot_sync(0xFFFFFFFFu, lbad);
        if (threadIdx.x == 0) s_i64 = (m == 0u) ? 1 : 0;
    }
    __syncthreads();
    const bool i64 = (s_i64 != 0);

    int hw = (blockIdx.x * blockDim.x + threadIdx.x) >> 4;
    int lane = threadIdx.x & 15;
    int nhw = (gridDim.x * blockDim.x) >> 4;

    if (i64) edge_loop<true>(feat, srcv, dstv, E, hw, lane, nhw);
    else     edge_loop<false>(feat, srcv, dstv, E, hw, lane, nhw);
}

// ---------------------------------------------------------------------------
// Packed f32x2 helpers (Blackwell double-rate fp32 path)
__device__ __forceinline__ unsigned long long pack2(float a, float b) {
    unsigned long long r;
    asm("mov.b64 %0, {%1, %2};" : "=l"(r) : "f"(a), "f"(b));
    return r;
}
__device__ __forceinline__ void unpack2(unsigned long long v, float& a, float& b) {
    asm("mov.b64 {%0, %1}, %2;" : "=f"(a), "=f"(b) : "l"(v));
}
#define FMA2(d, a, b) asm("fma.rn.f32x2 %0, %1, %2, %0;" : "+l"(d) : "l"(a), "l"(b))

// ---------------------------------------------------------------------------
// out = relu(X @ Wc + bias), X[n] = [feat[n] | neigh_sum[n]/max(deg,1)] (len 128)
// Wc = [W_self ; W_neigh]  (128 x 64)
// Block: 256 threads, tile = 128 nodes x 64 cols. Per-thread 8 nodes x 4 cols.
// Epilogue restores g_neigh rows and g_deg entries of this tile to zero.
__global__ __launch_bounds__(256) void out_gemm_kernel(
    const float* __restrict__ feat,
    const float* __restrict__ Ws,
    const float* __restrict__ Wn,
    const float* __restrict__ bias,
    float* __restrict__ out,
    int N) {
    __shared__ float Wc[128][68];   // padded stride keeps float4 16B-aligned
    __shared__ float Xs[16][132];
    __shared__ float invd[128];
    __shared__ float bsh[64];

    int tid = threadIdx.x;
    int nb = blockIdx.x * 128;

    // load combined weight matrix
    for (int i = tid; i < 64 * 64; i += 256) {
        int k = i >> 6, c = i & 63;
        Wc[k][c] = Ws[i];
        Wc[64 + k][c] = Wn[i];
    }
    if (tid < 64) bsh[tid] = bias[tid];
    if (tid < 128) {
        int gn = nb + tid;
        if (gn < N) {
            float dg = g_deg[gn];
            invd[tid] = 1.f / fmaxf(dg, 1.f);
            g_deg[gn] = 0.f;          // self-clean for next replay
        } else {
            invd[tid] = 1.f;
        }
    }
    __syncthreads();

    const int r0 = (tid >> 4) * 8;   // 8 nodes
    const int c0 = (tid & 15) * 4;   // 4 cols

    unsigned long long acc[8][2];
#pragma unroll
    for (int i = 0; i < 8; i++) { acc[i][0] = 0ull; acc[i][1] = 0ull; }

    // loading role: 2 threads per node, each loads 8 contiguous k-values
    const int nl = tid >> 1;
    const int half = tid & 1;
    int gnl = nb + nl;
    if (gnl >= N) gnl = N - 1;  // clamped safe read; result masked at store
    const float iv = invd[nl];

#pragma unroll 1
    for (int kc = 0; kc < 8; kc++) {
        int kb = kc * 16 + half * 8;   // global k base for this thread's 8 values
        float4 a, b;
        if (kb < 64) {
            a = *reinterpret_cast<const float4*>(feat + (long long)gnl * 64 + kb);
            b = *reinterpret_cast<const float4*>(feat + (long long)gnl * 64 + kb + 4);
        } else {
            a = *reinterpret_cast<const float4*>(g_neigh + (long long)gnl * 64 + kb - 64);
            b = *reinterpret_cast<const float4*>(g_neigh + (long long)gnl * 64 + kb - 60);
            a.x *= iv; a.y *= iv; a.z *= iv; a.w *= iv;
            b.x *= iv; b.y *= iv; b.z *= iv; b.w *= iv;
        }
        __syncthreads();  // previous chunk fully consumed before overwrite
        int kk0 = half * 8;
        Xs[kk0 + 0][nl] = a.x; Xs[kk0 + 1][nl] = a.y;
        Xs[kk0 + 2][nl] = a.z; Xs[kk0 + 3][nl] = a.w;
        Xs[kk0 + 4][nl] = b.x; Xs[kk0 + 5][nl] = b.y;
        Xs[kk0 + 6][nl] = b.z; Xs[kk0 + 7][nl] = b.w;
        __syncthreads();

#pragma unroll
        for (int kk = 0; kk < 16; kk++) {
            int k = kc * 16 + kk;
            float4 w = *reinterpret_cast<const float4*>(&Wc[k][c0]);
            unsigned long long w01 = pack2(w.x, w.y);
            unsigned long long w23 = pack2(w.z, w.w);
            float4 xa = *reinterpret_cast<const float4*>(&Xs[kk][r0]);
            float4 xb = *reinterpret_cast<const float4*>(&Xs[kk][r0 + 4]);
            float xr[8] = {xa.x, xa.y, xa.z, xa.w, xb.x, xb.y, xb.z, xb.w};
#pragma unroll
            for (int i = 0; i < 8; i++) {
                unsigned long long xx = pack2(xr[i], xr[i]);
                FMA2(acc[i][0], xx, w01);
                FMA2(acc[i][1], xx, w23);
            }
        }
    }

    // epilogue: bias + relu + store; zero this tile's g_neigh for next replay.
    // All g_neigh reads by this block happened before the final __syncthreads
    // in the last loop iteration; no other block touches these rows.
    float b0 = bsh[c0], b1 = bsh[c0 + 1], b2 = bsh[c0 + 2], b3 = bsh[c0 + 3];
    float4 z4 = make_float4(0.f, 0.f, 0.f, 0.f);
#pragma unroll
    for (int i = 0; i < 8; i++) {
        int gn = nb + r0 + i;
        if (gn < N) {
            float o0, o1, o2, o3;
            unpack2(acc[i][0], o0, o1);
            unpack2(acc[i][1], o2, o3);
            float4 o;
            o.x = fmaxf(o0 + b0, 0.f);
            o.y = fmaxf(o1 + b1, 0.f);
            o.z = fmaxf(o2 + b2, 0.f);
            o.w = fmaxf(o3 + b3, 0.f);
            *reinterpret_cast<float4*>(out + (long long)gn * 64 + c0) = o;
            *reinterpret_cast<float4*>(g_neigh + (long long)gn * 64 + c0) = z4;
        }
    }
}

// ---------------------------------------------------------------------------
extern "C" void kernel_launch(void* const* d_in, const int* in_sizes, int n_in,
                              void* d_out, int out_size) {
    const float* feat = (const float*)d_in[0];
    const void* src   = d_in[1];
    const void* dst   = d_in[2];
    const float* Ws   = (const float*)d_in[3];
    const float* Wn   = (const float*)d_in[4];
    const float* bias = (const float*)d_in[5];
    float* out = (float*)d_out;

    int N = in_sizes[0] / D_IN;
    int E = in_sizes[1];

    edge_kernel<<<2048, 256>>>(feat, src, dst, E, N);
    int gblocks = (N + 127) / 128;
    out_gemm_kernel<<<gblocks, 256>>>(feat, Ws, Wn, bias, out, N);
}